// round 5
// baseline (speedup 1.0000x reference)
#include <cuda_runtime.h>
#include <cuda_fp16.h>
#include <cstdint>

// Problem constants (fixed by the dataset)
#define NNODES 50000
#define NBATCH 8
#define DFEAT  128
#define DCLASS 64
#define MROWS  (NNODES * NBATCH)   // 400000

// Scratch (device globals — no allocations allowed in kernel_launch)
__device__ __half g_sup[(size_t)MROWS * DFEAT];  // GEMM out / SpMM gather src
__device__ __half g_h1 [(size_t)MROWS * DFEAT];  // hidden 1 (fp16)
__device__ __half g_h2 [(size_t)MROWS * DFEAT];  // hidden 2 (fp16)
__device__ __half g_xh [(size_t)MROWS * DFEAT];  // x converted to fp16
__device__ __half g_W1h[DFEAT * DFEAT];
__device__ __half g_W2h[DFEAT * DFEAT];
__device__ __half g_W3h[DFEAT * DCLASS];
__device__ int    g_rowptr[NNODES + 1];
__device__ int2   g_edges[1600000 + 64];         // packed (col, val-bits)

static __device__ __forceinline__ uint32_t smem_u32(const void* p) {
    return (uint32_t)__cvta_generic_to_shared(p);
}

// ---------------------------------------------------------------------------
// CSR row_ptr from sorted edge_rows: row_ptr[i] = lower_bound(rows, i)
// ---------------------------------------------------------------------------
__global__ void build_rowptr_kernel(const int* __restrict__ rows, int E,
                                    int* __restrict__ rowptr, int N) {
    int i = blockIdx.x * blockDim.x + threadIdx.x;
    if (i > N) return;
    int lo = 0, hi = E;
    while (lo < hi) {
        int mid = (lo + hi) >> 1;
        if (rows[mid] < i) lo = mid + 1; else hi = mid;
    }
    rowptr[i] = lo;
}

// ---------------------------------------------------------------------------
// Pack (col, val) into one int2 per edge: single 8B broadcast load in SpMM
// ---------------------------------------------------------------------------
__global__ void pack_edges_kernel(const int* __restrict__ cols,
                                  const float* __restrict__ vals,
                                  int2* __restrict__ edges, int E) {
    int stride = gridDim.x * blockDim.x;
    for (int i = blockIdx.x * blockDim.x + threadIdx.x; i < E; i += stride)
        edges[i] = make_int2(cols[i], __float_as_int(vals[i]));
}

// ---------------------------------------------------------------------------
// float -> half convert (vectorized, n divisible by 4)
// ---------------------------------------------------------------------------
__global__ void f2h_kernel(const float4* __restrict__ in, uint2* __restrict__ out,
                           int n4) {
    int stride = gridDim.x * blockDim.x;
    for (int i = blockIdx.x * blockDim.x + threadIdx.x; i < n4; i += stride) {
        float4 v = in[i];
        __half2 a = __floats2half2_rn(v.x, v.y);
        __half2 b = __floats2half2_rn(v.z, v.w);
        uint2 o;
        o.x = *reinterpret_cast<uint32_t*>(&a);
        o.y = *reinterpret_cast<uint32_t*>(&b);
        out[i] = o;
    }
}

// All three weight matrices in one launch
__global__ void f2h3_kernel(const float4* __restrict__ a, uint2* __restrict__ oa, int na,
                            const float4* __restrict__ b, uint2* __restrict__ ob, int nb,
                            const float4* __restrict__ c, uint2* __restrict__ oc, int nc) {
    int stride = gridDim.x * blockDim.x;
    int total = na + nb + nc;
    for (int i = blockIdx.x * blockDim.x + threadIdx.x; i < total; i += stride) {
        const float4* src; uint2* dst; int j = i;
        if (j < na)            { src = a; dst = oa; }
        else if (j < na + nb)  { src = b; dst = ob; j -= na; }
        else                   { src = c; dst = oc; j -= na + nb; }
        float4 v = src[j];
        __half2 p = __floats2half2_rn(v.x, v.y);
        __half2 q = __floats2half2_rn(v.z, v.w);
        uint2 o;
        o.x = *reinterpret_cast<uint32_t*>(&p);
        o.y = *reinterpret_cast<uint32_t*>(&q);
        dst[j] = o;
    }
}

// ---------------------------------------------------------------------------
// Tensor-core GEMM: C[M][BN] = A[M][128] * W[128][BN], fp16 in, fp32 acc,
// fp16 out. BM=128, 256 threads (8 warps as 2m x 4n), K split into 2 halves.
// ---------------------------------------------------------------------------
template<int BN>
__global__ __launch_bounds__(256)
void mma_gemm(const __half* __restrict__ A, const __half* __restrict__ W,
              __half* __restrict__ C) {
    constexpr int LDA = 72;
    constexpr int LDB = BN + 8;
    constexpr int NT  = BN / 32;
    __shared__ __half As[128 * LDA];
    __shared__ __half Bs[64 * LDB];

    const int tid  = threadIdx.x;
    const int warp = tid >> 5, lane = tid & 31;
    const int wm = (warp & 1) * 64;
    const int wn = (warp >> 1) * (BN / 4);
    const size_t m0 = (size_t)blockIdx.x * 128;

    float acc[4][NT][4];
#pragma unroll
    for (int mt = 0; mt < 4; mt++)
#pragma unroll
        for (int nt = 0; nt < NT; nt++)
#pragma unroll
            for (int i = 0; i < 4; i++) acc[mt][nt][i] = 0.f;

#pragma unroll
    for (int kc = 0; kc < 2; kc++) {
        const __half* Agp = A + m0 * 128 + kc * 64;
#pragma unroll
        for (int i = 0; i < 4; i++) {
            int c = tid + i * 256;
            int r = c >> 3, col = (c & 7) * 8;
            *reinterpret_cast<uint4*>(&As[r * LDA + col]) =
                *reinterpret_cast<const uint4*>(&Agp[(size_t)r * 128 + col]);
        }
        constexpr int CPR = BN / 8;
        const __half* Wgp = W + (size_t)kc * 64 * BN;
#pragma unroll
        for (int i = 0; i < 64 * CPR / 256; i++) {
            int c = tid + i * 256;
            int r = c / CPR, col = (c % CPR) * 8;
            *reinterpret_cast<uint4*>(&Bs[r * LDB + col]) =
                *reinterpret_cast<const uint4*>(&Wgp[(size_t)r * BN + col]);
        }
        __syncthreads();

#pragma unroll
        for (int k0 = 0; k0 < 64; k0 += 16) {
            uint32_t a[4][4];
#pragma unroll
            for (int mt = 0; mt < 4; mt++) {
                int row = wm + mt * 16 + (lane & 15);
                int col = k0 + (lane >> 4) * 8;
                uint32_t ad = smem_u32(&As[row * LDA + col]);
                asm volatile(
                    "ldmatrix.sync.aligned.m8n8.x4.shared.b16 {%0,%1,%2,%3}, [%4];"
                    : "=r"(a[mt][0]), "=r"(a[mt][1]), "=r"(a[mt][2]), "=r"(a[mt][3])
                    : "r"(ad));
            }
            uint32_t b[NT][2];
#pragma unroll
            for (int nt = 0; nt < NT; nt++) {
                int row = k0 + (lane & 15);
                int col = wn + nt * 8;
                uint32_t ad = smem_u32(&Bs[row * LDB + col]);
                asm volatile(
                    "ldmatrix.sync.aligned.m8n8.x2.trans.shared.b16 {%0,%1}, [%2];"
                    : "=r"(b[nt][0]), "=r"(b[nt][1]) : "r"(ad));
            }
#pragma unroll
            for (int mt = 0; mt < 4; mt++)
#pragma unroll
                for (int nt = 0; nt < NT; nt++)
                    asm volatile(
                        "mma.sync.aligned.m16n8k16.row.col.f32.f16.f16.f32 "
                        "{%0,%1,%2,%3}, {%4,%5,%6,%7}, {%8,%9}, {%0,%1,%2,%3};"
                        : "+f"(acc[mt][nt][0]), "+f"(acc[mt][nt][1]),
                          "+f"(acc[mt][nt][2]), "+f"(acc[mt][nt][3])
                        : "r"(a[mt][0]), "r"(a[mt][1]), "r"(a[mt][2]), "r"(a[mt][3]),
                          "r"(b[nt][0]), "r"(b[nt][1]));
        }
        __syncthreads();
    }

    const int gid = lane >> 2, qid = lane & 3;
#pragma unroll
    for (int mt = 0; mt < 4; mt++) {
#pragma unroll
        for (int nt = 0; nt < NT; nt++) {
            int r  = wm + mt * 16 + gid;
            int cc = wn + nt * 8 + qid * 2;
            __half2 lo = __floats2half2_rn(acc[mt][nt][0], acc[mt][nt][1]);
            __half2 hi = __floats2half2_rn(acc[mt][nt][2], acc[mt][nt][3]);
            *reinterpret_cast<__half2*>(&C[(m0 + r) * BN + cc]) = lo;
            *reinterpret_cast<__half2*>(&C[(m0 + r + 8) * BN + cc]) = hi;
        }
    }
}

// ---------------------------------------------------------------------------
// SpMM, one warp = one node x ALL 8 batches. Packed (col,val) read once per
// edge per node. F=128: lane owns features [4t..4t+3] (one uint2 per batch).
// MODE 0: h_out(fp16) = relu(agg + bias + res(fp16))
// grid = N/4, block = 128 (4 warps)
// ---------------------------------------------------------------------------
__global__ __launch_bounds__(128)
void spmm8_128(const __half* __restrict__ sup,
               const int*  __restrict__ rowptr,
               const int2* __restrict__ edges,
               const float* __restrict__ bias,
               const __half* __restrict__ res,
               __half* __restrict__ out, int N) {
    const int node = blockIdx.x * 4 + (threadIdx.x >> 5);
    const int t    = threadIdx.x & 31;
    const int e0 = rowptr[node];
    const int e1 = rowptr[node + 1];

    const uint2* supv = reinterpret_cast<const uint2*>(sup);   // 4 halves per elem
    const size_t SB = (size_t)N * 32;                          // batch stride (uint2)

    float acc[8][4];
#pragma unroll
    for (int b = 0; b < 8; b++)
#pragma unroll
        for (int i = 0; i < 4; i++) acc[b][i] = 0.f;

#pragma unroll 2
    for (int e = e0; e < e1; e++) {
        int2 ev = edges[e];
        float v = __int_as_float(ev.y);
        size_t base = (size_t)ev.x * 32 + t;
        uint2 u[8];
#pragma unroll
        for (int b = 0; b < 8; b++) u[b] = supv[base + b * SB];
#pragma unroll
        for (int b = 0; b < 8; b++) {
            float2 p = __half22float2(*reinterpret_cast<__half2*>(&u[b].x));
            float2 q = __half22float2(*reinterpret_cast<__half2*>(&u[b].y));
            acc[b][0] += v * p.x; acc[b][1] += v * p.y;
            acc[b][2] += v * q.x; acc[b][3] += v * q.y;
        }
    }

    const float4 bi = reinterpret_cast<const float4*>(bias)[t];
    const uint2* resv = reinterpret_cast<const uint2*>(res);
    uint2* outv = reinterpret_cast<uint2*>(out);
#pragma unroll
    for (int b = 0; b < 8; b++) {
        size_t o = ((size_t)b * N + node) * 32 + t;
        uint2 rv = resv[o];
        float2 rp = __half22float2(*reinterpret_cast<__half2*>(&rv.x));
        float2 rq = __half22float2(*reinterpret_cast<__half2*>(&rv.y));
        float r0 = fmaxf(acc[b][0] + bi.x + rp.x, 0.f);
        float r1 = fmaxf(acc[b][1] + bi.y + rp.y, 0.f);
        float r2 = fmaxf(acc[b][2] + bi.z + rq.x, 0.f);
        float r3 = fmaxf(acc[b][3] + bi.w + rq.y, 0.f);
        __half2 o01 = __floats2half2_rn(r0, r1);
        __half2 o23 = __floats2half2_rn(r2, r3);
        uint2 ov;
        ov.x = *reinterpret_cast<uint32_t*>(&o01);
        ov.y = *reinterpret_cast<uint32_t*>(&o23);
        outv[o] = ov;
    }
}

// F=64 final layer: lane owns features [2t..2t+1] (one uint32 per batch).
// out = sigmoid(relu(agg + bias)), fp32 output.
__global__ __launch_bounds__(128)
void spmm8_64(const __half* __restrict__ sup,
              const int*  __restrict__ rowptr,
              const int2* __restrict__ edges,
              const float* __restrict__ bias,
              float* __restrict__ out, int N) {
    const int node = blockIdx.x * 4 + (threadIdx.x >> 5);
    const int t    = threadIdx.x & 31;
    const int e0 = rowptr[node];
    const int e1 = rowptr[node + 1];

    const uint32_t* supv = reinterpret_cast<const uint32_t*>(sup); // 2 halves
    const size_t SB = (size_t)N * 32;                              // batch stride (uint32)

    float accx[8], accy[8];
#pragma unroll
    for (int b = 0; b < 8; b++) { accx[b] = 0.f; accy[b] = 0.f; }

#pragma unroll 2
    for (int e = e0; e < e1; e++) {
        int2 ev = edges[e];
        float v = __int_as_float(ev.y);
        size_t base = (size_t)ev.x * 32 + t;
        uint32_t u[8];
#pragma unroll
        for (int b = 0; b < 8; b++) u[b] = supv[base + b * SB];
#pragma unroll
        for (int b = 0; b < 8; b++) {
            float2 p = __half22float2(*reinterpret_cast<__half2*>(&u[b]));
            accx[b] += v * p.x; accy[b] += v * p.y;
        }
    }

    const float2 bi = reinterpret_cast<const float2*>(bias)[t];
#pragma unroll
    for (int b = 0; b < 8; b++) {
        float rx = fmaxf(accx[b] + bi.x, 0.f);
        float ry = fmaxf(accy[b] + bi.y, 0.f);
        rx = 1.f / (1.f + __expf(-rx));
        ry = 1.f / (1.f + __expf(-ry));
        size_t o = ((size_t)b * N + node) * 32 + t;   // float2 units
        reinterpret_cast<float2*>(out)[o] = make_float2(rx, ry);
    }
}

// ---------------------------------------------------------------------------
// Launch: prep + 3 GCN layers
// ---------------------------------------------------------------------------
extern "C" void kernel_launch(void* const* d_in, const int* in_sizes, int n_in,
                              void* d_out, int out_size) {
    const float* x    = (const float*)d_in[0];
    const int*   rows = (const int*)  d_in[1];
    const int*   cols = (const int*)  d_in[2];
    const float* vals = (const float*)d_in[3];
    const float* W1   = (const float*)d_in[4];
    const float* b1   = (const float*)d_in[5];
    const float* W2   = (const float*)d_in[6];
    const float* b2   = (const float*)d_in[7];
    const float* W3   = (const float*)d_in[8];
    const float* b3   = (const float*)d_in[9];
    float* out = (float*)d_out;

    const int N = NNODES;
    const int E = in_sizes[1];

    __half *sup, *h1, *h2, *xh, *w1h, *w2h, *w3h; int* rp; int2* edges;
    cudaGetSymbolAddress((void**)&sup, g_sup);
    cudaGetSymbolAddress((void**)&h1,  g_h1);
    cudaGetSymbolAddress((void**)&h2,  g_h2);
    cudaGetSymbolAddress((void**)&xh,  g_xh);
    cudaGetSymbolAddress((void**)&w1h, g_W1h);
    cudaGetSymbolAddress((void**)&w2h, g_W2h);
    cudaGetSymbolAddress((void**)&w3h, g_W3h);
    cudaGetSymbolAddress((void**)&rp,  g_rowptr);
    cudaGetSymbolAddress((void**)&edges, g_edges);

    // Prep: CSR offsets, packed edges, fp16 conversions
    build_rowptr_kernel<<<(N + 256) / 256, 256>>>(rows, E, rp, N);
    pack_edges_kernel<<<1024, 256>>>(cols, vals, edges, E);
    f2h_kernel<<<2048, 256>>>((const float4*)x, (uint2*)xh, MROWS * DFEAT / 4);
    f2h3_kernel<<<40, 256>>>((const float4*)W1, (uint2*)w1h, DFEAT * DFEAT / 4,
                             (const float4*)W2, (uint2*)w2h, DFEAT * DFEAT / 4,
                             (const float4*)W3, (uint2*)w3h, DFEAT * DCLASS / 4);

    const int gemm_grid = MROWS / 128;   // 3125
    const int spmm_grid = N / 4;         // 12500

    // Layer 1: h1 = relu(spmm(x @ W1) + b1 + x)
    mma_gemm<128><<<gemm_grid, 256>>>(xh, w1h, sup);
    spmm8_128<<<spmm_grid, 128>>>(sup, rp, edges, b1, xh, h1, N);

    // Layer 2: h2 = relu(spmm(h1 @ W2) + b2 + h1)
    mma_gemm<128><<<gemm_grid, 256>>>(h1, w2h, sup);
    spmm8_128<<<spmm_grid, 128>>>(sup, rp, edges, b2, h1, h2, N);

    // Layer 3: out = sigmoid(relu(spmm(h2 @ W3) + b3))
    mma_gemm<64><<<gemm_grid, 256>>>(h2, w3h, sup);
    spmm8_64<<<spmm_grid, 128>>>(sup, rp, edges, b3, out, N);
}

// round 6
// speedup vs baseline: 1.4335x; 1.4335x over previous
#include <cuda_runtime.h>
#include <cuda_fp16.h>
#include <cstdint>

// Problem constants (fixed by the dataset)
#define NNODES 50000
#define NBATCH 8
#define DFEAT  128
#define DCLASS 64
#define MROWS  (NNODES * NBATCH)   // 400000

// Scratch (device globals — no allocations allowed in kernel_launch)
__device__ __half g_sup[(size_t)MROWS * DFEAT];  // GEMM out / SpMM gather src
__device__ __half g_h1 [(size_t)MROWS * DFEAT];  // hidden 1 (fp16)
__device__ __half g_h2 [(size_t)MROWS * DFEAT];  // hidden 2 (fp16)
__device__ __half g_W1h[DFEAT * DFEAT];
__device__ __half g_W2h[DFEAT * DFEAT];
__device__ __half g_W3h[DFEAT * DCLASS];
__device__ int    g_rowptr[NNODES + 1];
__device__ int2   g_edges[1600000 + 64];         // packed (col, val-bits)

static __device__ __forceinline__ uint32_t smem_u32(const void* p) {
    return (uint32_t)__cvta_generic_to_shared(p);
}

// ---------------------------------------------------------------------------
// CSR row_ptr from sorted edge_rows: row_ptr[i] = lower_bound(rows, i)
// ---------------------------------------------------------------------------
__global__ void build_rowptr_kernel(const int* __restrict__ rows, int E,
                                    int* __restrict__ rowptr, int N) {
    int i = blockIdx.x * blockDim.x + threadIdx.x;
    if (i > N) return;
    int lo = 0, hi = E;
    while (lo < hi) {
        int mid = (lo + hi) >> 1;
        if (rows[mid] < i) lo = mid + 1; else hi = mid;
    }
    rowptr[i] = lo;
}

// ---------------------------------------------------------------------------
// Pack (col, val) into one int2 per edge: single 8B broadcast load in SpMM
// ---------------------------------------------------------------------------
__global__ void pack_edges_kernel(const int* __restrict__ cols,
                                  const float* __restrict__ vals,
                                  int2* __restrict__ edges, int E) {
    int stride = gridDim.x * blockDim.x;
    for (int i = blockIdx.x * blockDim.x + threadIdx.x; i < E; i += stride)
        edges[i] = make_int2(cols[i], __float_as_int(vals[i]));
}

// All three weight matrices in one launch
__global__ void f2h3_kernel(const float4* __restrict__ a, uint2* __restrict__ oa, int na,
                            const float4* __restrict__ b, uint2* __restrict__ ob, int nb,
                            const float4* __restrict__ c, uint2* __restrict__ oc, int nc) {
    int stride = gridDim.x * blockDim.x;
    int total = na + nb + nc;
    for (int i = blockIdx.x * blockDim.x + threadIdx.x; i < total; i += stride) {
        const float4* src; uint2* dst; int j = i;
        if (j < na)            { src = a; dst = oa; }
        else if (j < na + nb)  { src = b; dst = ob; j -= na; }
        else                   { src = c; dst = oc; j -= na + nb; }
        float4 v = src[j];
        __half2 p = __floats2half2_rn(v.x, v.y);
        __half2 q = __floats2half2_rn(v.z, v.w);
        uint2 o;
        o.x = *reinterpret_cast<uint32_t*>(&p);
        o.y = *reinterpret_cast<uint32_t*>(&q);
        dst[j] = o;
    }
}

// ---------------------------------------------------------------------------
// Tensor-core GEMM: C[M][BN] = A[M][128] * W[128][BN], fp16 in (or fp32 A,
// converted while staging), fp32 acc, fp16 out. BM=128, 256 threads
// (8 warps as 2m x 4n), K split into 2 halves of 64.
// ---------------------------------------------------------------------------
template<int BN, bool AF32>
__global__ __launch_bounds__(256)
void mma_gemm(const void* __restrict__ Ap, const __half* __restrict__ W,
              __half* __restrict__ C) {
    constexpr int LDA = 72;
    constexpr int LDB = BN + 8;
    constexpr int NT  = BN / 32;
    __shared__ __half As[128 * LDA];
    __shared__ __half Bs[64 * LDB];

    const int tid  = threadIdx.x;
    const int warp = tid >> 5, lane = tid & 31;
    const int wm = (warp & 1) * 64;
    const int wn = (warp >> 1) * (BN / 4);
    const size_t m0 = (size_t)blockIdx.x * 128;

    float acc[4][NT][4];
#pragma unroll
    for (int mt = 0; mt < 4; mt++)
#pragma unroll
        for (int nt = 0; nt < NT; nt++)
#pragma unroll
            for (int i = 0; i < 4; i++) acc[mt][nt][i] = 0.f;

#pragma unroll
    for (int kc = 0; kc < 2; kc++) {
        // Stage A k-half: 128 rows x 64 halves
        if (AF32) {
            const float* Agp = (const float*)Ap + m0 * 128 + kc * 64;
#pragma unroll
            for (int i = 0; i < 8; i++) {
                int c = tid + i * 256;              // 2048 float4 chunks
                int r = c >> 4, col = (c & 15) * 4;
                float4 v = *reinterpret_cast<const float4*>(
                    &Agp[(size_t)r * 128 + col]);
                __half2 p = __floats2half2_rn(v.x, v.y);
                __half2 q = __floats2half2_rn(v.z, v.w);
                uint2 o;
                o.x = *reinterpret_cast<uint32_t*>(&p);
                o.y = *reinterpret_cast<uint32_t*>(&q);
                *reinterpret_cast<uint2*>(&As[r * LDA + col]) = o;
            }
        } else {
            const __half* Agp = (const __half*)Ap + m0 * 128 + kc * 64;
#pragma unroll
            for (int i = 0; i < 4; i++) {
                int c = tid + i * 256;              // 1024 16B chunks
                int r = c >> 3, col = (c & 7) * 8;
                *reinterpret_cast<uint4*>(&As[r * LDA + col]) =
                    *reinterpret_cast<const uint4*>(&Agp[(size_t)r * 128 + col]);
            }
        }
        constexpr int CPR = BN / 8;
        const __half* Wgp = W + (size_t)kc * 64 * BN;
#pragma unroll
        for (int i = 0; i < 64 * CPR / 256; i++) {
            int c = tid + i * 256;
            int r = c / CPR, col = (c % CPR) * 8;
            *reinterpret_cast<uint4*>(&Bs[r * LDB + col]) =
                *reinterpret_cast<const uint4*>(&Wgp[(size_t)r * BN + col]);
        }
        __syncthreads();

#pragma unroll
        for (int k0 = 0; k0 < 64; k0 += 16) {
            uint32_t a[4][4];
#pragma unroll
            for (int mt = 0; mt < 4; mt++) {
                int row = wm + mt * 16 + (lane & 15);
                int col = k0 + (lane >> 4) * 8;
                uint32_t ad = smem_u32(&As[row * LDA + col]);
                asm volatile(
                    "ldmatrix.sync.aligned.m8n8.x4.shared.b16 {%0,%1,%2,%3}, [%4];"
                    : "=r"(a[mt][0]), "=r"(a[mt][1]), "=r"(a[mt][2]), "=r"(a[mt][3])
                    : "r"(ad));
            }
            uint32_t b[NT][2];
#pragma unroll
            for (int nt = 0; nt < NT; nt++) {
                int row = k0 + (lane & 15);
                int col = wn + nt * 8;
                uint32_t ad = smem_u32(&Bs[row * LDB + col]);
                asm volatile(
                    "ldmatrix.sync.aligned.m8n8.x2.trans.shared.b16 {%0,%1}, [%2];"
                    : "=r"(b[nt][0]), "=r"(b[nt][1]) : "r"(ad));
            }
#pragma unroll
            for (int mt = 0; mt < 4; mt++)
#pragma unroll
                for (int nt = 0; nt < NT; nt++)
                    asm volatile(
                        "mma.sync.aligned.m16n8k16.row.col.f32.f16.f16.f32 "
                        "{%0,%1,%2,%3}, {%4,%5,%6,%7}, {%8,%9}, {%0,%1,%2,%3};"
                        : "+f"(acc[mt][nt][0]), "+f"(acc[mt][nt][1]),
                          "+f"(acc[mt][nt][2]), "+f"(acc[mt][nt][3])
                        : "r"(a[mt][0]), "r"(a[mt][1]), "r"(a[mt][2]), "r"(a[mt][3]),
                          "r"(b[nt][0]), "r"(b[nt][1]));
        }
        __syncthreads();
    }

    const int gid = lane >> 2, qid = lane & 3;
#pragma unroll
    for (int mt = 0; mt < 4; mt++) {
#pragma unroll
        for (int nt = 0; nt < NT; nt++) {
            int r  = wm + mt * 16 + gid;
            int cc = wn + nt * 8 + qid * 2;
            __half2 lo = __floats2half2_rn(acc[mt][nt][0], acc[mt][nt][1]);
            __half2 hi = __floats2half2_rn(acc[mt][nt][2], acc[mt][nt][3]);
            *reinterpret_cast<__half2*>(&C[(m0 + r) * BN + cc]) = lo;
            *reinterpret_cast<__half2*>(&C[(m0 + r + 8) * BN + cc]) = hi;
        }
    }
}

// ---------------------------------------------------------------------------
// SpMM + fused epilogue (R4-proven structure). One warp per (node, batch),
// 4 warps/block, grid (N, NBATCH/4) -> batch-phased L2 working set.
// F=128: lane owns features [4t..4t+3] (uint2, 8B gather per lane).
// out(fp16) = relu(agg + bias + res); res fp32 (layer1) or fp16 (layer2).
// ---------------------------------------------------------------------------
template<bool RF32>
__global__ __launch_bounds__(128)
void spmm_128(const __half* __restrict__ sup,
              const int*  __restrict__ rowptr,
              const int2* __restrict__ edges,
              const float* __restrict__ bias,
              const void* __restrict__ res,
              __half* __restrict__ out, int N) {
    const int node = blockIdx.x;
    const int b    = blockIdx.y * 4 + (threadIdx.x >> 5);
    const int t    = threadIdx.x & 31;

    const uint2* supb = reinterpret_cast<const uint2*>(sup) + (size_t)b * N * 32;
    const int e0 = rowptr[node];
    const int e1 = rowptr[node + 1];

    float a0 = 0.f, a1 = 0.f, a2 = 0.f, a3 = 0.f;
    int e = e0;
    for (; e + 4 <= e1; e += 4) {
        int2 ev0 = edges[e],     ev1 = edges[e + 1];
        int2 ev2 = edges[e + 2], ev3 = edges[e + 3];
        uint2 u0 = supb[(size_t)ev0.x * 32 + t];
        uint2 u1 = supb[(size_t)ev1.x * 32 + t];
        uint2 u2 = supb[(size_t)ev2.x * 32 + t];
        uint2 u3 = supb[(size_t)ev3.x * 32 + t];
        float v0 = __int_as_float(ev0.y), v1 = __int_as_float(ev1.y);
        float v2 = __int_as_float(ev2.y), v3 = __int_as_float(ev3.y);
        float2 p, q;
        p = __half22float2(*reinterpret_cast<__half2*>(&u0.x));
        q = __half22float2(*reinterpret_cast<__half2*>(&u0.y));
        a0 += v0 * p.x; a1 += v0 * p.y; a2 += v0 * q.x; a3 += v0 * q.y;
        p = __half22float2(*reinterpret_cast<__half2*>(&u1.x));
        q = __half22float2(*reinterpret_cast<__half2*>(&u1.y));
        a0 += v1 * p.x; a1 += v1 * p.y; a2 += v1 * q.x; a3 += v1 * q.y;
        p = __half22float2(*reinterpret_cast<__half2*>(&u2.x));
        q = __half22float2(*reinterpret_cast<__half2*>(&u2.y));
        a0 += v2 * p.x; a1 += v2 * p.y; a2 += v2 * q.x; a3 += v2 * q.y;
        p = __half22float2(*reinterpret_cast<__half2*>(&u3.x));
        q = __half22float2(*reinterpret_cast<__half2*>(&u3.y));
        a0 += v3 * p.x; a1 += v3 * p.y; a2 += v3 * q.x; a3 += v3 * q.y;
    }
    for (; e < e1; e++) {
        int2 ev = edges[e];
        float v = __int_as_float(ev.y);
        uint2 u = supb[(size_t)ev.x * 32 + t];
        float2 p = __half22float2(*reinterpret_cast<__half2*>(&u.x));
        float2 q = __half22float2(*reinterpret_cast<__half2*>(&u.y));
        a0 += v * p.x; a1 += v * p.y; a2 += v * q.x; a3 += v * q.y;
    }

    const float4 bi = reinterpret_cast<const float4*>(bias)[t];
    a0 += bi.x; a1 += bi.y; a2 += bi.z; a3 += bi.w;

    const size_t row = (size_t)b * N + node;
    if (RF32) {
        float4 rv = reinterpret_cast<const float4*>(res)[row * 32 + t];
        a0 += rv.x; a1 += rv.y; a2 += rv.z; a3 += rv.w;
    } else {
        uint2 rv = reinterpret_cast<const uint2*>(res)[row * 32 + t];
        float2 rp = __half22float2(*reinterpret_cast<__half2*>(&rv.x));
        float2 rq = __half22float2(*reinterpret_cast<__half2*>(&rv.y));
        a0 += rp.x; a1 += rp.y; a2 += rq.x; a3 += rq.y;
    }
    a0 = fmaxf(a0, 0.f); a1 = fmaxf(a1, 0.f);
    a2 = fmaxf(a2, 0.f); a3 = fmaxf(a3, 0.f);
    __half2 o01 = __floats2half2_rn(a0, a1);
    __half2 o23 = __floats2half2_rn(a2, a3);
    uint2 ov;
    ov.x = *reinterpret_cast<uint32_t*>(&o01);
    ov.y = *reinterpret_cast<uint32_t*>(&o23);
    reinterpret_cast<uint2*>(out)[row * 32 + t] = ov;
}

// F=64 final layer: lane owns features [2t..2t+1] (4B gather per lane).
// out(fp32) = sigmoid(relu(agg + bias))
__global__ __launch_bounds__(128)
void spmm_64(const __half* __restrict__ sup,
             const int*  __restrict__ rowptr,
             const int2* __restrict__ edges,
             const float* __restrict__ bias,
             float* __restrict__ out, int N) {
    const int node = blockIdx.x;
    const int b    = blockIdx.y * 4 + (threadIdx.x >> 5);
    const int t    = threadIdx.x & 31;

    const uint32_t* supb = reinterpret_cast<const uint32_t*>(sup) + (size_t)b * N * 32;
    const int e0 = rowptr[node];
    const int e1 = rowptr[node + 1];

    float a0 = 0.f, a1 = 0.f;
    int e = e0;
    for (; e + 4 <= e1; e += 4) {
        int2 ev0 = edges[e],     ev1 = edges[e + 1];
        int2 ev2 = edges[e + 2], ev3 = edges[e + 3];
        uint32_t u0 = supb[(size_t)ev0.x * 32 + t];
        uint32_t u1 = supb[(size_t)ev1.x * 32 + t];
        uint32_t u2 = supb[(size_t)ev2.x * 32 + t];
        uint32_t u3 = supb[(size_t)ev3.x * 32 + t];
        float v0 = __int_as_float(ev0.y), v1 = __int_as_float(ev1.y);
        float v2 = __int_as_float(ev2.y), v3 = __int_as_float(ev3.y);
        float2 s;
        s = __half22float2(*reinterpret_cast<__half2*>(&u0));
        a0 += v0 * s.x; a1 += v0 * s.y;
        s = __half22float2(*reinterpret_cast<__half2*>(&u1));
        a0 += v1 * s.x; a1 += v1 * s.y;
        s = __half22float2(*reinterpret_cast<__half2*>(&u2));
        a0 += v2 * s.x; a1 += v2 * s.y;
        s = __half22float2(*reinterpret_cast<__half2*>(&u3));
        a0 += v3 * s.x; a1 += v3 * s.y;
    }
    for (; e < e1; e++) {
        int2 ev = edges[e];
        float v = __int_as_float(ev.y);
        uint32_t u = supb[(size_t)ev.x * 32 + t];
        float2 s = __half22float2(*reinterpret_cast<__half2*>(&u));
        a0 += v * s.x; a1 += v * s.y;
    }

    const float2 bi = reinterpret_cast<const float2*>(bias)[t];
    a0 = fmaxf(a0 + bi.x, 0.f);
    a1 = fmaxf(a1 + bi.y, 0.f);
    a0 = 1.f / (1.f + __expf(-a0));
    a1 = 1.f / (1.f + __expf(-a1));
    const size_t row = (size_t)b * N + node;
    reinterpret_cast<float2*>(out)[row * 32 + t] = make_float2(a0, a1);
}

// ---------------------------------------------------------------------------
// Launch: prep + 3 GCN layers
// ---------------------------------------------------------------------------
extern "C" void kernel_launch(void* const* d_in, const int* in_sizes, int n_in,
                              void* d_out, int out_size) {
    const float* x    = (const float*)d_in[0];
    const int*   rows = (const int*)  d_in[1];
    const int*   cols = (const int*)  d_in[2];
    const float* vals = (const float*)d_in[3];
    const float* W1   = (const float*)d_in[4];
    const float* b1   = (const float*)d_in[5];
    const float* W2   = (const float*)d_in[6];
    const float* b2   = (const float*)d_in[7];
    const float* W3   = (const float*)d_in[8];
    const float* b3   = (const float*)d_in[9];
    float* out = (float*)d_out;

    const int N = NNODES;
    const int E = in_sizes[1];

    __half *sup, *h1, *h2, *w1h, *w2h, *w3h; int* rp; int2* edges;
    cudaGetSymbolAddress((void**)&sup, g_sup);
    cudaGetSymbolAddress((void**)&h1,  g_h1);
    cudaGetSymbolAddress((void**)&h2,  g_h2);
    cudaGetSymbolAddress((void**)&w1h, g_W1h);
    cudaGetSymbolAddress((void**)&w2h, g_W2h);
    cudaGetSymbolAddress((void**)&w3h, g_W3h);
    cudaGetSymbolAddress((void**)&rp,  g_rowptr);
    cudaGetSymbolAddress((void**)&edges, g_edges);

    // Prep: CSR offsets, packed edges, fp16 weight conversions
    build_rowptr_kernel<<<(N + 256) / 256, 256>>>(rows, E, rp, N);
    pack_edges_kernel<<<1024, 256>>>(cols, vals, edges, E);
    f2h3_kernel<<<40, 256>>>((const float4*)W1, (uint2*)w1h, DFEAT * DFEAT / 4,
                             (const float4*)W2, (uint2*)w2h, DFEAT * DFEAT / 4,
                             (const float4*)W3, (uint2*)w3h, DFEAT * DCLASS / 4);

    const int gemm_grid = MROWS / 128;         // 3125
    const dim3 spmm_grid(N, NBATCH / 4);       // batch-phased

    // Layer 1: h1 = relu(spmm(x @ W1) + b1 + x)   (A and residual in fp32)
    mma_gemm<128, true><<<gemm_grid, 256>>>(x, w1h, sup);
    spmm_128<true><<<spmm_grid, 128>>>(sup, rp, edges, b1, x, h1, N);

    // Layer 2: h2 = relu(spmm(h1 @ W2) + b2 + h1)
    mma_gemm<128, false><<<gemm_grid, 256>>>(h1, w2h, sup);
    spmm_128<false><<<spmm_grid, 128>>>(sup, rp, edges, b2, h1, h2, N);

    // Layer 3: out = sigmoid(relu(spmm(h2 @ W3) + b3))
    mma_gemm<64, false><<<gemm_grid, 256>>>(h2, w3h, sup);
    spmm_64<<<spmm_grid, 128>>>(sup, rp, edges, b3, out, N);
}